// round 6
// baseline (speedup 1.0000x reference)
#include <cuda_runtime.h>

// Problem constants: x[B,C,H,W] f32, gamma/beta [N,C], out [B, N*C, H, W]
#define B_   32
#define C_   64
#define HW_  1024          // H*W
#define N_   16
#define HW4_ 256           // HW in float4 units
#define NPLANES_ (B_ * C_) // 2048
#define INV_CNT (1.0f / (float)(B_ * HW_))  // 1/32768

// Scratch (static device globals; no allocation)
__device__ float g_psum[NPLANES_];
__device__ float g_psq [NPLANES_];
__device__ float g_sg  [N_ * C_];
__device__ float g_sb  [N_ * C_];

// ---------------------------------------------------------------------------
// Kernel 1: per-(b,c)-plane partial sums. One block per 4KB plane.
// 128 threads x 2 float4 = 1024 floats.
// ---------------------------------------------------------------------------
__global__ __launch_bounds__(128) void reduce_kernel(const float4* __restrict__ x4) {
    const int bc  = blockIdx.x;        // = b*C + c
    const int tid = threadIdx.x;       // 0..127
    const float4* p = x4 + bc * HW4_;

    float4 a = p[tid];
    float4 b = p[tid + 128];
    float s = a.x + a.y + a.z + a.w + b.x + b.y + b.z + b.w;
    float q = a.x*a.x + a.y*a.y + a.z*a.z + a.w*a.w
            + b.x*b.x + b.y*b.y + b.z*b.z + b.w*b.w;

    #pragma unroll
    for (int o = 16; o > 0; o >>= 1) {
        s += __shfl_down_sync(0xFFFFFFFFu, s, o);
        q += __shfl_down_sync(0xFFFFFFFFu, q, o);
    }

    __shared__ float ss[4], qq[4];
    const int w = tid >> 5;
    if ((tid & 31) == 0) { ss[w] = s; qq[w] = q; }
    __syncthreads();
    if (tid == 0) {
        g_psum[bc] = ss[0] + ss[1] + ss[2] + ss[3];
        g_psq [bc] = qq[0] + qq[1] + qq[2] + qq[3];
    }
}

// ---------------------------------------------------------------------------
// Kernel 2: finalize mean/inv per channel, fold gamma/beta into (sg, sb).
// 1 block, 1024 threads. Threads 0..63 handle channels, then all 1024
// threads compute one (n,c) pair each.
// ---------------------------------------------------------------------------
__global__ __launch_bounds__(1024) void finalize_kernel(const float* __restrict__ gamma,
                                                        const float* __restrict__ beta) {
    __shared__ float m_s[C_];
    __shared__ float i_s[C_];

    const int t = threadIdx.x;
    if (t < C_) {
        float s = 0.f, q = 0.f;
        #pragma unroll 8
        for (int b = 0; b < B_; b++) {
            s += g_psum[b * C_ + t];   // coalesced across the 64 threads
            q += g_psq [b * C_ + t];
        }
        const float mean = s * INV_CNT;
        const float var  = q * INV_CNT - mean * mean;  // biased var (torch BN)
        m_s[t] = mean;
        i_s[t] = rsqrtf(var + 1e-5f);
    }
    __syncthreads();

    const int c  = t & (C_ - 1);
    const float g  = gamma[t];   // [N,C] linear == t
    const float be = beta [t];
    const float sg = g * i_s[c];
    g_sg[t] = sg;
    g_sb[t] = fmaf(-sg, m_s[c], be);
}

// ---------------------------------------------------------------------------
// Kernel 3: apply. One block per (b,c) plane (c is block-uniform), each
// thread: 1 float4 load of x (L2 hit), 16 streaming float4 stores.
// ---------------------------------------------------------------------------
__global__ __launch_bounds__(256) void apply_kernel(const float4* __restrict__ x4,
                                                    float4* __restrict__ out4) {
    const int bc  = blockIdx.x;          // b*C + c
    const int c   = bc & (C_ - 1);
    const int b   = bc >> 6;
    const int hw4 = threadIdx.x;         // 0..255

    const float4 v = __ldg(&x4[bc * HW4_ + hw4]);

    // out linear (float4 units): (b*(N*C) + n*C + c) * HW4 + hw4
    const int base = (b * (N_ * C_) + c) * HW4_ + hw4;

    #pragma unroll
    for (int n = 0; n < N_; n++) {
        const float s = __ldg(&g_sg[n * C_ + c]);   // uniform per block -> L1 broadcast
        const float t = __ldg(&g_sb[n * C_ + c]);
        float4 o;
        o.x = fmaf(s, v.x, t);
        o.y = fmaf(s, v.y, t);
        o.z = fmaf(s, v.z, t);
        o.w = fmaf(s, v.w, t);
        __stcs(&out4[base + n * (C_ * HW4_)], o);   // streaming store: no L2 reuse
    }
}

// ---------------------------------------------------------------------------
extern "C" void kernel_launch(void* const* d_in, const int* in_sizes, int n_in,
                              void* d_out, int out_size) {
    const float4* x4    = (const float4*)d_in[0];  // x [32,64,32,32]
    const float*  gamma = (const float*) d_in[1];  // [16,64]
    const float*  beta  = (const float*) d_in[2];  // [16,64]
    float4*       out4  = (float4*)d_out;          // [32,1024,32,32]

    reduce_kernel  <<<NPLANES_, 128>>>(x4);
    finalize_kernel<<<1, 1024>>>(gamma, beta);
    apply_kernel   <<<NPLANES_, 256>>>(x4, out4);
}

// round 7
// speedup vs baseline: 1.0043x; 1.0043x over previous
#include <cuda_runtime.h>

// Problem constants: x[B,C,H,W] f32, gamma/beta [N,C], out [B, N*C, H, W]
#define B_   32
#define C_   64
#define HW_  1024          // H*W
#define N_   16
#define HW4_ 256           // HW in float4 units
#define NPLANES_ (B_ * C_) // 2048
#define INV_CNT (1.0f / (float)(B_ * HW_))  // 1/32768

// Scratch (static device globals; no allocation)
__device__ float g_psum[NPLANES_];
__device__ float g_psq [NPLANES_];
__device__ float g_sg  [N_ * C_];
__device__ float g_sb  [N_ * C_];

// ---------------------------------------------------------------------------
// Kernel 1: per-(b,c)-plane partial sums. One block per 4KB plane.
// 128 threads x 2 float4 = 1024 floats.
// ---------------------------------------------------------------------------
__global__ __launch_bounds__(128) void reduce_kernel(const float4* __restrict__ x4) {
    const int bc  = blockIdx.x;        // = b*C + c
    const int tid = threadIdx.x;       // 0..127
    const float4* p = x4 + bc * HW4_;

    float4 a = p[tid];
    float4 b = p[tid + 128];
    float s = a.x + a.y + a.z + a.w + b.x + b.y + b.z + b.w;
    float q = a.x*a.x + a.y*a.y + a.z*a.z + a.w*a.w
            + b.x*b.x + b.y*b.y + b.z*b.z + b.w*b.w;

    #pragma unroll
    for (int o = 16; o > 0; o >>= 1) {
        s += __shfl_down_sync(0xFFFFFFFFu, s, o);
        q += __shfl_down_sync(0xFFFFFFFFu, q, o);
    }

    __shared__ float ss[4], qq[4];
    const int w = tid >> 5;
    if ((tid & 31) == 0) { ss[w] = s; qq[w] = q; }
    __syncthreads();
    if (tid == 0) {
        g_psum[bc] = ss[0] + ss[1] + ss[2] + ss[3];
        g_psq [bc] = qq[0] + qq[1] + qq[2] + qq[3];
    }
}

// ---------------------------------------------------------------------------
// Kernel 2: finalize mean/inv per channel, fold gamma/beta into (sg, sb).
// 1 block, 1024 threads. Threads 0..63 handle channels, then all 1024
// threads compute one (n,c) pair each.
// ---------------------------------------------------------------------------
__global__ __launch_bounds__(1024) void finalize_kernel(const float* __restrict__ gamma,
                                                        const float* __restrict__ beta) {
    __shared__ float m_s[C_];
    __shared__ float i_s[C_];

    const int t = threadIdx.x;
    if (t < C_) {
        float s = 0.f, q = 0.f;
        #pragma unroll 8
        for (int b = 0; b < B_; b++) {
            s += g_psum[b * C_ + t];   // coalesced across the 64 threads
            q += g_psq [b * C_ + t];
        }
        const float mean = s * INV_CNT;
        const float var  = q * INV_CNT - mean * mean;  // biased var (torch BN)
        m_s[t] = mean;
        i_s[t] = rsqrtf(var + 1e-5f);
    }
    __syncthreads();

    const int c  = t & (C_ - 1);
    const float g  = gamma[t];   // [N,C] linear == t
    const float be = beta [t];
    const float sg = g * i_s[c];
    g_sg[t] = sg;
    g_sb[t] = fmaf(-sg, m_s[c], be);
}

// ---------------------------------------------------------------------------
// Kernel 3: apply. One block per (b,c) plane (c is block-uniform), each
// thread: 1 float4 load of x (L2 hit), 16 streaming float4 stores.
// ---------------------------------------------------------------------------
__global__ __launch_bounds__(256) void apply_kernel(const float4* __restrict__ x4,
                                                    float4* __restrict__ out4) {
    const int bc  = blockIdx.x;          // b*C + c
    const int c   = bc & (C_ - 1);
    const int b   = bc >> 6;
    const int hw4 = threadIdx.x;         // 0..255

    const float4 v = __ldg(&x4[bc * HW4_ + hw4]);

    // out linear (float4 units): (b*(N*C) + n*C + c) * HW4 + hw4
    const int base = (b * (N_ * C_) + c) * HW4_ + hw4;

    #pragma unroll
    for (int n = 0; n < N_; n++) {
        const float s = __ldg(&g_sg[n * C_ + c]);   // uniform per block -> L1 broadcast
        const float t = __ldg(&g_sb[n * C_ + c]);
        float4 o;
        o.x = fmaf(s, v.x, t);
        o.y = fmaf(s, v.y, t);
        o.z = fmaf(s, v.z, t);
        o.w = fmaf(s, v.w, t);
        __stcs(&out4[base + n * (C_ * HW4_)], o);   // streaming store: no L2 reuse
    }
}

// ---------------------------------------------------------------------------
extern "C" void kernel_launch(void* const* d_in, const int* in_sizes, int n_in,
                              void* d_out, int out_size) {
    const float4* x4    = (const float4*)d_in[0];  // x [32,64,32,32]
    const float*  gamma = (const float*) d_in[1];  // [16,64]
    const float*  beta  = (const float*) d_in[2];  // [16,64]
    float4*       out4  = (float4*)d_out;          // [32,1024,32,32]

    reduce_kernel  <<<NPLANES_, 128>>>(x4);
    finalize_kernel<<<1, 1024>>>(gamma, beta);
    apply_kernel   <<<NPLANES_, 256>>>(x4, out4);
}

// round 8
// speedup vs baseline: 1.0054x; 1.0011x over previous
#include <cuda_runtime.h>

// Problem constants: x[B,C,H,W] f32, gamma/beta [N,C], out [B, N*C, H, W]
#define B_   32
#define C_   64
#define HW_  1024          // H*W
#define N_   16
#define HW4_ 256           // HW in float4 units
#define NPLANES_ (B_ * C_) // 2048
#define INV_CNT (1.0f / (float)(B_ * HW_))  // 1/32768

// Scratch (static device globals; no allocation)
__device__ float g_psum[NPLANES_];
__device__ float g_psq [NPLANES_];
__device__ float g_sg  [N_ * C_];
__device__ float g_sb  [N_ * C_];

// ---------------------------------------------------------------------------
// Kernel 1: per-(b,c)-plane partial sums. One block per 4KB plane.
// 128 threads x 2 float4 = 1024 floats.
// ---------------------------------------------------------------------------
__global__ __launch_bounds__(128) void reduce_kernel(const float4* __restrict__ x4) {
    const int bc  = blockIdx.x;        // = b*C + c
    const int tid = threadIdx.x;       // 0..127
    const float4* p = x4 + bc * HW4_;

    float4 a = p[tid];
    float4 b = p[tid + 128];
    float s = a.x + a.y + a.z + a.w + b.x + b.y + b.z + b.w;
    float q = a.x*a.x + a.y*a.y + a.z*a.z + a.w*a.w
            + b.x*b.x + b.y*b.y + b.z*b.z + b.w*b.w;

    #pragma unroll
    for (int o = 16; o > 0; o >>= 1) {
        s += __shfl_down_sync(0xFFFFFFFFu, s, o);
        q += __shfl_down_sync(0xFFFFFFFFu, q, o);
    }

    __shared__ float ss[4], qq[4];
    const int w = tid >> 5;
    if ((tid & 31) == 0) { ss[w] = s; qq[w] = q; }
    __syncthreads();
    if (tid == 0) {
        g_psum[bc] = ss[0] + ss[1] + ss[2] + ss[3];
        g_psq [bc] = qq[0] + qq[1] + qq[2] + qq[3];
    }
}

// ---------------------------------------------------------------------------
// Kernel 2: finalize mean/inv per channel, fold gamma/beta into (sg, sb).
// 1 block, 1024 threads. Threads 0..63 handle channels, then all 1024
// threads compute one (n,c) pair each.
// ---------------------------------------------------------------------------
__global__ __launch_bounds__(1024) void finalize_kernel(const float* __restrict__ gamma,
                                                        const float* __restrict__ beta) {
    __shared__ float m_s[C_];
    __shared__ float i_s[C_];

    const int t = threadIdx.x;
    if (t < C_) {
        float s = 0.f, q = 0.f;
        #pragma unroll 8
        for (int b = 0; b < B_; b++) {
            s += g_psum[b * C_ + t];   // coalesced across the 64 threads
            q += g_psq [b * C_ + t];
        }
        const float mean = s * INV_CNT;
        const float var  = q * INV_CNT - mean * mean;  // biased var (torch BN)
        m_s[t] = mean;
        i_s[t] = rsqrtf(var + 1e-5f);
    }
    __syncthreads();

    const int c  = t & (C_ - 1);
    const float g  = gamma[t];   // [N,C] linear == t
    const float be = beta [t];
    const float sg = g * i_s[c];
    g_sg[t] = sg;
    g_sb[t] = fmaf(-sg, m_s[c], be);
}

// ---------------------------------------------------------------------------
// Kernel 3: apply. One block per (b,c) plane (c is block-uniform), each
// thread: 1 float4 load of x (L2 hit), 16 streaming float4 stores.
// ---------------------------------------------------------------------------
__global__ __launch_bounds__(256) void apply_kernel(const float4* __restrict__ x4,
                                                    float4* __restrict__ out4) {
    const int bc  = blockIdx.x;          // b*C + c
    const int c   = bc & (C_ - 1);
    const int b   = bc >> 6;
    const int hw4 = threadIdx.x;         // 0..255

    const float4 v = __ldg(&x4[bc * HW4_ + hw4]);

    // out linear (float4 units): (b*(N*C) + n*C + c) * HW4 + hw4
    const int base = (b * (N_ * C_) + c) * HW4_ + hw4;

    #pragma unroll
    for (int n = 0; n < N_; n++) {
        const float s = __ldg(&g_sg[n * C_ + c]);   // uniform per block -> L1 broadcast
        const float t = __ldg(&g_sb[n * C_ + c]);
        float4 o;
        o.x = fmaf(s, v.x, t);
        o.y = fmaf(s, v.y, t);
        o.z = fmaf(s, v.z, t);
        o.w = fmaf(s, v.w, t);
        __stcs(&out4[base + n * (C_ * HW4_)], o);   // streaming store: no L2 reuse
    }
}

// ---------------------------------------------------------------------------
extern "C" void kernel_launch(void* const* d_in, const int* in_sizes, int n_in,
                              void* d_out, int out_size) {
    const float4* x4    = (const float4*)d_in[0];  // x [32,64,32,32]
    const float*  gamma = (const float*) d_in[1];  // [16,64]
    const float*  beta  = (const float*) d_in[2];  // [16,64]
    float4*       out4  = (float4*)d_out;          // [32,1024,32,32]

    reduce_kernel  <<<NPLANES_, 128>>>(x4);
    finalize_kernel<<<1, 1024>>>(gamma, beta);
    apply_kernel   <<<NPLANES_, 256>>>(x4, out4);
}